// round 1
// baseline (speedup 1.0000x reference)
#include <cuda_runtime.h>
#include <cuda_bf16.h>
#include <cstdint>

// MX e4m3 quantize-dequantize, block size 32 along rows.
// out = qdq(x / s) * s, s derived from per-block amax with bf16 rounding.

__device__ __forceinline__ float quant_e4m3(float a) {
    float mag = fabsf(a);
    // floor(log2(mag)) via exponent field (exact for normals; zero/denormal
    // give biased exp ~0 -> e=-127 which the clamp below maps to -6, matching
    // the reference's min_exp clamp).
    int e = (int)(__float_as_uint(mag) >> 23) - 127;
    e = max(e, -6);
    float pe  = __uint_as_float((uint32_t)(e + 127) << 23);  // 2^e
    float inv = __uint_as_float((uint32_t)(130 - e) << 23);  // 2^(3-e)  (lsh/pe)
    float m = mag * inv;                  // exact power-of-2 scaling
    float q = floorf(m + 0.5f);           // round-half-away (mag >= 0)
    float outmag = q * (pe * 0.125f);     // exact rescale
    outmag = fminf(outmag, 448.0f);       // saturate_normals
    return copysignf(outmag, a);
}

__global__ void __launch_bounds__(256)
mxq_kernel(const float* __restrict__ x, float* __restrict__ y, int nblk) {
    int b = blockIdx.x * blockDim.x + threadIdx.x;
    if (b >= nblk) return;

    const float4* xv = reinterpret_cast<const float4*>(x) + (size_t)b * 8;
    float4*       yv = reinterpret_cast<float4*>(y)       + (size_t)b * 8;

    float4 v[8];
#pragma unroll
    for (int i = 0; i < 8; i++) v[i] = __ldcs(xv + i);

    float amax = 0.0f;
#pragma unroll
    for (int i = 0; i < 8; i++) {
        amax = fmaxf(amax, fmaxf(fmaxf(fabsf(v[i].x), fabsf(v[i].y)),
                                 fmaxf(fabsf(v[i].z), fabsf(v[i].w))));
    }

    // scales = bf16(amax / 448)
    float sc = __bfloat162float(__float2bfloat16(amax / 448.0f));
    // s = floor_bf16(sc*256 + 0.5) * 2^-8, all in bf16 semantics
    float t = sc * 256.0f;                                    // exact (exp shift)
    float u = __bfloat162float(__float2bfloat16(t + 0.5f));   // bf16 add (RN)
    float s = floorf(u) * 0.00390625f;                        // exact * 2^-8
    if (s == 0.0f) s = 1.0f;                                  // zero scale -> 1

#pragma unroll
    for (int i = 0; i < 8; i++) {
        float4 o;
        o.x = quant_e4m3(v[i].x / s) * s;
        o.y = quant_e4m3(v[i].y / s) * s;
        o.z = quant_e4m3(v[i].z / s) * s;
        o.w = quant_e4m3(v[i].w / s) * s;
        __stcs(yv + i, o);
    }
}

extern "C" void kernel_launch(void* const* d_in, const int* in_sizes, int n_in,
                              void* d_out, int out_size) {
    const float* x = (const float*)d_in[0];
    float* y = (float*)d_out;
    int n = in_sizes[0];          // 8192*8192 = 67,108,864
    int nblk = n / 32;            // 2,097,152 blocks of 32
    int threads = 256;
    int grid = (nblk + threads - 1) / threads;
    mxq_kernel<<<grid, threads>>>(x, y, nblk);
}

// round 2
// speedup vs baseline: 1.7148x; 1.7148x over previous
#include <cuda_runtime.h>
#include <cuda_bf16.h>
#include <cstdint>

// MX e4m3 quantize-dequantize, block size 32 along rows.
// Coalesced layout: lane l handles float4 (warpBase + i*32 + l).
// One 32-float MX block = 8 consecutive float4s = one 8-lane group at fixed i.

__device__ __forceinline__ float quant_e4m3(float a) {
    float mag = fabsf(a);
    int e = (int)(__float_as_uint(mag) >> 23) - 127;   // floor(log2|a|), exact for normals
    e = max(e, -6);                                     // min_exp clamp (absorbs 0/denorm)
    float pe  = __uint_as_float((uint32_t)(e + 127) << 23);  // 2^e
    float inv = __uint_as_float((uint32_t)(130 - e) << 23);  // 2^(3-e)
    float m = mag * inv;                   // exact power-of-2 scaling
    float q = floorf(m + 0.5f);            // round-half-away (mag >= 0)
    float outmag = q * (pe * 0.125f);      // exact rescale
    outmag = fminf(outmag, 448.0f);        // saturate_normals
    return copysignf(outmag, a);
}

__device__ __forceinline__ float mx_scale(float amax) {
    // scales = bf16(amax / 448); s = floor_bf16(sc*256 + 0.5) * 2^-8; 0 -> 1
    float sc = __bfloat162float(__float2bfloat16(amax * (1.0f / 448.0f) ));
    // NOTE: reference does a true division amax/448. 1/448 is not a power of 2,
    // so reciprocal-multiply could differ in the last ulp BEFORE the bf16
    // round. Use real division to be safe:
    sc = __bfloat162float(__float2bfloat16(amax / 448.0f));
    float t = sc * 256.0f;                                   // exact exp shift
    float u = __bfloat162float(__float2bfloat16(t + 0.5f));  // bf16 add (RN)
    float s = floorf(u) * 0.00390625f;                       // exact * 2^-8
    return (s == 0.0f) ? 1.0f : s;
}

__global__ void __launch_bounds__(256)
mxq_kernel(const float4* __restrict__ x, float4* __restrict__ y, int nf4) {
    int tid  = blockIdx.x * blockDim.x + threadIdx.x;
    int warp = tid >> 5;
    int lane = tid & 31;
    size_t base = (size_t)warp * 256 + lane;   // warp covers 256 float4 = 1KB*... (4KB)
    if ((size_t)warp * 256 >= (size_t)nf4) return;

    float4 v[8];
#pragma unroll
    for (int i = 0; i < 8; i++) v[i] = __ldcs(x + base + i * 32);

    float s[8];
#pragma unroll
    for (int i = 0; i < 8; i++) {
        float m = fmaxf(fmaxf(fabsf(v[i].x), fabsf(v[i].y)),
                        fmaxf(fabsf(v[i].z), fabsf(v[i].w)));
        // reduce amax over the 8-lane group owning this MX block
        m = fmaxf(m, __shfl_xor_sync(0xFFFFFFFFu, m, 1));
        m = fmaxf(m, __shfl_xor_sync(0xFFFFFFFFu, m, 2));
        m = fmaxf(m, __shfl_xor_sync(0xFFFFFFFFu, m, 4));
        s[i] = mx_scale(m);
    }

#pragma unroll
    for (int i = 0; i < 8; i++) {
        float4 o;
        o.x = quant_e4m3(v[i].x / s[i]) * s[i];
        o.y = quant_e4m3(v[i].y / s[i]) * s[i];
        o.z = quant_e4m3(v[i].z / s[i]) * s[i];
        o.w = quant_e4m3(v[i].w / s[i]) * s[i];
        __stcs(y + base + i * 32, o);
    }
}

extern "C" void kernel_launch(void* const* d_in, const int* in_sizes, int n_in,
                              void* d_out, int out_size) {
    const float4* x = (const float4*)d_in[0];
    float4* y = (float4*)d_out;
    int n = in_sizes[0];            // 67,108,864 floats
    int nf4 = n / 4;                // 16,777,216 float4
    int threads = 256;
    int nthreads_total = nf4 / 8;   // 8 float4 per thread
    int grid = (nthreads_total + threads - 1) / threads;
    mxq_kernel<<<grid, threads>>>(x, y, nf4);
}

// round 4
// speedup vs baseline: 1.7221x; 1.0043x over previous
#include <cuda_runtime.h>
#include <cuda_bf16.h>
#include <cstdint>

// MX e4m3 quantize-dequantize, block size 32 along rows.
// Coalesced: lane l handles float4 (warpBase + i*32 + l); one MX block =
// 8 consecutive float4s = one aligned 8-lane group at fixed i.
// Per-element division x/s replaced by per-block reciprocal + Markstein
// FMA correction (bit-identical to correctly-rounded x/s).

__device__ __forceinline__ float quant_e4m3_div(float x, float s, float r) {
    // correctly-rounded x / s via Markstein (r = RN(1/s)):
    float q0 = __fmul_rn(x, r);
    float d  = __fmaf_rn(__fmaf_rn(-q0, s, x), r, q0);

    float mag = fabsf(d);
    int e = (int)(__float_as_uint(mag) >> 23) - 127;        // floor(log2|d|), exact for normals
    e = max(e, -6);                                          // min_exp clamp (absorbs 0/denorm)
    float inv  = __uint_as_float((uint32_t)(130 - e) << 23); // 2^(3-e)
    float pout = __uint_as_float((uint32_t)(e + 124) << 23); // 2^(e-3)
    float q = floorf(__fmaf_rn(mag, inv, 0.5f));             // round-half-away (mag*inv exact)
    float outmag = fminf(__fmul_rn(q, pout), 448.0f);        // exact rescale + saturate
    return copysignf(outmag, d);
}

__device__ __forceinline__ float mx_scale(float amax) {
    // scales = bf16(amax / 448); s = floor_bf16(sc*256 + 0.5) * 2^-8; 0 -> 1
    float sc = __bfloat162float(__float2bfloat16(amax / 448.0f));
    float t = sc * 256.0f;                                   // exact exp shift
    float u = __bfloat162float(__float2bfloat16(t + 0.5f));  // bf16 add (RN)
    float s = floorf(u) * 0.00390625f;                       // exact * 2^-8
    return (s == 0.0f) ? 1.0f : s;
}

__global__ void __launch_bounds__(256)
mxq_kernel(const float4* __restrict__ x, float4* __restrict__ y, int nf4) {
    int tid  = blockIdx.x * blockDim.x + threadIdx.x;
    int warp = tid >> 5;
    int lane = tid & 31;
    size_t base = (size_t)warp * 256 + lane;   // warp covers 256 float4 (4 KB)
    if ((size_t)warp * 256 >= (size_t)nf4) return;

    float4 v[8];
#pragma unroll
    for (int i = 0; i < 8; i++) v[i] = __ldcs(x + base + i * 32);

    float s[8], r[8];
#pragma unroll
    for (int i = 0; i < 8; i++) {
        float m = fmaxf(fmaxf(fabsf(v[i].x), fabsf(v[i].y)),
                        fmaxf(fabsf(v[i].z), fabsf(v[i].w)));
        // amax over the 8-lane group owning this MX block
        m = fmaxf(m, __shfl_xor_sync(0xFFFFFFFFu, m, 1));
        m = fmaxf(m, __shfl_xor_sync(0xFFFFFFFFu, m, 2));
        m = fmaxf(m, __shfl_xor_sync(0xFFFFFFFFu, m, 4));
        s[i] = mx_scale(m);
        r[i] = 1.0f / s[i];                    // one real division per block
    }

#pragma unroll
    for (int i = 0; i < 8; i++) {
        float4 o;
        o.x = quant_e4m3_div(v[i].x, s[i], r[i]) * s[i];
        o.y = quant_e4m3_div(v[i].y, s[i], r[i]) * s[i];
        o.z = quant_e4m3_div(v[i].z, s[i], r[i]) * s[i];
        o.w = quant_e4m3_div(v[i].w, s[i], r[i]) * s[i];
        __stcs(y + base + i * 32, o);
    }
}

extern "C" void kernel_launch(void* const* d_in, const int* in_sizes, int n_in,
                              void* d_out, int out_size) {
    const float4* x = (const float4*)d_in[0];
    float4* y = (float4*)d_out;
    int n = in_sizes[0];            // 67,108,864 floats
    int nf4 = n / 4;                // 16,777,216 float4
    int threads = 256;
    int nthreads_total = nf4 / 8;   // 8 float4 per thread
    int grid = (nthreads_total + threads - 1) / threads;
    mxq_kernel<<<grid, threads>>>(x, y, nf4);
}

// round 5
// speedup vs baseline: 1.7295x; 1.0043x over previous
#include <cuda_runtime.h>
#include <cuda_bf16.h>
#include <cstdint>

// MX e4m3 quantize-dequantize, block size 32 along rows.
// Coalesced: lane l handles float4 (warpBase + i*32 + l); one MX block =
// 8 consecutive float4s = one aligned 8-lane group at fixed i.
// 4 float4 per thread (vs 8) to cut register pressure and raise occupancy.
// Per-element division via per-block reciprocal + Markstein FMA correction
// (bit-identical to correctly-rounded x/s).

__device__ __forceinline__ float quant_e4m3_div(float x, float s, float r) {
    // correctly-rounded x / s via Markstein (r = RN(1/s)):
    float q0 = __fmul_rn(x, r);
    float d  = __fmaf_rn(__fmaf_rn(-q0, s, x), r, q0);

    float mag = fabsf(d);
    int e = (int)(__float_as_uint(mag) >> 23) - 127;        // floor(log2|d|), exact for normals
    e = max(e, -6);                                          // min_exp clamp (absorbs 0/denorm)
    float inv  = __uint_as_float((uint32_t)(130 - e) << 23); // 2^(3-e)
    float pout = __uint_as_float((uint32_t)(e + 124) << 23); // 2^(e-3)
    float q = floorf(__fmaf_rn(mag, inv, 0.5f));             // round-half-away (mag*inv exact)
    float outmag = fminf(__fmul_rn(q, pout), 448.0f);        // exact rescale + saturate
    return copysignf(outmag, d);
}

__device__ __forceinline__ float mx_scale(float amax) {
    // scales = bf16(amax / 448); s = floor_bf16(sc*256 + 0.5) * 2^-8; 0 -> 1
    float sc = __bfloat162float(__float2bfloat16(amax / 448.0f));
    float t = sc * 256.0f;                                   // exact exp shift
    float u = __bfloat162float(__float2bfloat16(t + 0.5f));  // bf16 add (RN)
    float s = floorf(u) * 0.00390625f;                       // exact * 2^-8
    return (s == 0.0f) ? 1.0f : s;
}

__global__ void __launch_bounds__(256)
mxq_kernel(const float4* __restrict__ x, float4* __restrict__ y, int nf4) {
    int tid  = blockIdx.x * blockDim.x + threadIdx.x;
    int warp = tid >> 5;
    int lane = tid & 31;
    size_t base = (size_t)warp * 128 + lane;   // warp covers 128 float4 (2 KB)
    if ((size_t)warp * 128 >= (size_t)nf4) return;

    float4 v[4];
#pragma unroll
    for (int i = 0; i < 4; i++) v[i] = __ldcs(x + base + i * 32);

    float s[4], r[4];
#pragma unroll
    for (int i = 0; i < 4; i++) {
        float m = fmaxf(fmaxf(fabsf(v[i].x), fabsf(v[i].y)),
                        fmaxf(fabsf(v[i].z), fabsf(v[i].w)));
        // amax over the 8-lane group owning this MX block
        m = fmaxf(m, __shfl_xor_sync(0xFFFFFFFFu, m, 1));
        m = fmaxf(m, __shfl_xor_sync(0xFFFFFFFFu, m, 2));
        m = fmaxf(m, __shfl_xor_sync(0xFFFFFFFFu, m, 4));
        s[i] = mx_scale(m);
        r[i] = 1.0f / s[i];                    // one real division per block
    }

#pragma unroll
    for (int i = 0; i < 4; i++) {
        float4 o;
        o.x = quant_e4m3_div(v[i].x, s[i], r[i]) * s[i];
        o.y = quant_e4m3_div(v[i].y, s[i], r[i]) * s[i];
        o.z = quant_e4m3_div(v[i].z, s[i], r[i]) * s[i];
        o.w = quant_e4m3_div(v[i].w, s[i], r[i]) * s[i];
        __stcs(y + base + i * 32, o);
    }
}

extern "C" void kernel_launch(void* const* d_in, const int* in_sizes, int n_in,
                              void* d_out, int out_size) {
    const float4* x = (const float4*)d_in[0];
    float4* y = (float4*)d_out;
    int n = in_sizes[0];            // 67,108,864 floats
    int nf4 = n / 4;                // 16,777,216 float4
    int threads = 256;
    int nthreads_total = nf4 / 4;   // 4 float4 per thread
    int grid = (nthreads_total + threads - 1) / threads;
    mxq_kernel<<<grid, threads>>>(x, y, nf4);
}

// round 6
// speedup vs baseline: 1.7315x; 1.0012x over previous
#include <cuda_runtime.h>
#include <cuda_bf16.h>
#include <cstdint>

// MX e4m3 quantize-dequantize, block size 32 along rows.
// Coalesced: lane l handles float4 (warpBase + i*32 + l); one MX block =
// 8 consecutive float4s = one aligned 8-lane group at fixed i.
// Quantizer uses exponent-field bit arithmetic and fuses the final *s into
// the rescale via exact power-of-two integer math; x/s via per-block
// reciprocal + Markstein FMA correction. All steps bit-identical to the
// reference rounding sequence.

__device__ __forceinline__ float mx_scale(float amax) {
    // sc = bf16(RN(amax/448)) ; RN division via Markstein with r448=RN(1/448)
    const float r448 = 1.0f / 448.0f;              // constant-folded RN(1/448)
    float q0 = __fmul_rn(amax, r448);
    float dv = __fmaf_rn(__fmaf_rn(-q0, 448.0f, amax), r448, q0);
    float sc = __bfloat162float(__float2bfloat16(dv));
    // s = floor_bf16(sc*256 + 0.5) * 2^-8 (bf16 semantics), 0 -> 1
    float t = sc * 256.0f;                                   // exact exp shift
    float u = __bfloat162float(__float2bfloat16(t + 0.5f));  // bf16 add (RN)
    float s = floorf(u) * 0.00390625f;                       // exact * 2^-8
    return (s == 0.0f) ? 1.0f : s;
}

// out = copysign(min(round_half_away(|x/s| * 2^(3-e)) * 2^(e-3), 448), x/s) * s
// with e = max(floor(log2|x/s|), -6). sB = s_bits - 0x41000000, c448s = 448*s.
__device__ __forceinline__ float qdq_e4m3(float x, float s, float r,
                                          uint32_t sB, float c448s) {
    // correctly-rounded d = x / s (Markstein, r = RN(1/s))
    float q0 = __fmul_rn(x, r);
    float d  = __fmaf_rn(__fmaf_rn(-q0, s, x), r, q0);

    uint32_t db  = __float_as_uint(d);
    uint32_t mb  = db & 0x7FFFFFFFu;                       // |d|
    uint32_t peb = max(mb & 0x7F800000u, 0x3C800000u);     // 2^e, e>=-6 (0/denorm ok)
    float inv = __uint_as_float(0x80800000u - peb);        // 2^(3-e)
    float ps  = __uint_as_float(peb + sB);                 // 2^(e-3) * s  (exact)
    float q = floorf(__fmaf_rn(__uint_as_float(mb), inv, 0.5f)); // half-away
    float outmag = fminf(__fmul_rn(q, ps), c448s);         // clamp == min(q*pout,448)*s
    return __uint_as_float(__float_as_uint(outmag) | (db & 0x80000000u));
}

__global__ void __launch_bounds__(256)
mxq_kernel(const float4* __restrict__ x, float4* __restrict__ y, int nf4) {
    int tid  = blockIdx.x * blockDim.x + threadIdx.x;
    int warp = tid >> 5;
    int lane = tid & 31;
    size_t base = (size_t)warp * 128 + lane;   // warp covers 128 float4 (2 KB)
    if ((size_t)warp * 128 >= (size_t)nf4) return;

    float4 v[4];
#pragma unroll
    for (int i = 0; i < 4; i++) v[i] = __ldcs(x + base + i * 32);

    float s[4], r[4], c448s[4];
    uint32_t sB[4];
#pragma unroll
    for (int i = 0; i < 4; i++) {
        float m = fmaxf(fmaxf(fabsf(v[i].x), fabsf(v[i].y)),
                        fmaxf(fabsf(v[i].z), fabsf(v[i].w)));
        // amax over the 8-lane group owning this MX block
        m = fmaxf(m, __shfl_xor_sync(0xFFFFFFFFu, m, 1));
        m = fmaxf(m, __shfl_xor_sync(0xFFFFFFFFu, m, 2));
        m = fmaxf(m, __shfl_xor_sync(0xFFFFFFFFu, m, 4));
        s[i] = mx_scale(m);
        r[i] = 1.0f / s[i];                            // RN reciprocal per block
        sB[i] = __float_as_uint(s[i]) - 0x41000000u;   // fold *2^-3 * s
        c448s[i] = 448.0f * s[i];                      // exact (s has <=8 mant bits)
    }

#pragma unroll
    for (int i = 0; i < 4; i++) {
        float4 o;
        o.x = qdq_e4m3(v[i].x, s[i], r[i], sB[i], c448s[i]);
        o.y = qdq_e4m3(v[i].y, s[i], r[i], sB[i], c448s[i]);
        o.z = qdq_e4m3(v[i].z, s[i], r[i], sB[i], c448s[i]);
        o.w = qdq_e4m3(v[i].w, s[i], r[i], sB[i], c448s[i]);
        __stcs(y + base + i * 32, o);
    }
}

extern "C" void kernel_launch(void* const* d_in, const int* in_sizes, int n_in,
                              void* d_out, int out_size) {
    const float4* x = (const float4*)d_in[0];
    float4* y = (float4*)d_out;
    int n = in_sizes[0];            // 67,108,864 floats
    int nf4 = n / 4;                // 16,777,216 float4
    int threads = 256;
    int nthreads_total = nf4 / 4;   // 4 float4 per thread
    int grid = (nthreads_total + threads - 1) / threads;
    mxq_kernel<<<grid, threads>>>(x, y, nf4);
}